// round 1
// baseline (speedup 1.0000x reference)
#include <cuda_runtime.h>
#include <math.h>

// Problem constants
#define BATCH   4096
#define IN_DIM  1024
#define OUT_DIM 1024
#define GRIDSZ  8
#define K_BASE  1024                   // silu(x) features
#define K_SPL   (IN_DIM * GRIDSZ)      // 8192 (cos block, then sin block)
#define K_TOT   (K_BASE + 2 * K_SPL)   // 17408

// Tiling
#define BM 128
#define BN 128
#define BK 32
#define SSTRIDE 36   // smem row stride (floats), padded vs 32 to kill bank conflicts

__device__ __forceinline__ unsigned f2tf32(float f) {
    unsigned r;
    asm("cvt.rna.tf32.f32 %0, %1;" : "=r"(r) : "f"(f));
    return r;
}

// Compute 8 consecutive virtual-K features for one batch row.
// kc = global k index of chunk start (multiple of 8; regions are 32-aligned so
// a chunk never straddles a region boundary).
__device__ __forceinline__ void feat8(const float* __restrict__ xrow, int kc, float* f) {
    if (kc < K_BASE) {
        float4 v0 = *reinterpret_cast<const float4*>(xrow + kc);
        float4 v1 = *reinterpret_cast<const float4*>(xrow + kc + 4);
        float vv[8] = {v0.x, v0.y, v0.z, v0.w, v1.x, v1.y, v1.z, v1.w};
#pragma unroll
        for (int j = 0; j < 8; j++) {
            float xx = vv[j];
            f[j] = __fdividef(xx, 1.0f + __expf(-xx));   // silu
        }
    } else {
        const bool is_cos = kc < (K_BASE + K_SPL);
        const int  i = (kc - (is_cos ? K_BASE : (K_BASE + K_SPL))) >> 3;
        float xx = xrow[i];
        float s1, c1;
        __sincosf(xx, &s1, &c1);
        float cg = c1, sg = s1;               // angle 1*x
        f[0] = is_cos ? cg : sg;
#pragma unroll
        for (int j = 1; j < 8; j++) {         // angle (j+1)*x via addition formulas
            float cn = cg * c1 - sg * s1;
            float sn = sg * c1 + cg * s1;
            cg = cn; sg = sn;
            f[j] = is_cos ? cg : sg;
        }
    }
}

// Compute 8 consecutive virtual-K weights for one output row o.
__device__ __forceinline__ void wgt8(const float* __restrict__ sb,
                                     const float* __restrict__ ss,
                                     const float* __restrict__ cf,
                                     int o, int kc, float* w) {
    if (kc < K_BASE) {
        const float* p = sb + (size_t)o * IN_DIM + kc;
        float4 v0 = *reinterpret_cast<const float4*>(p);
        float4 v1 = *reinterpret_cast<const float4*>(p + 4);
        w[0] = v0.x; w[1] = v0.y; w[2] = v0.z; w[3] = v0.w;
        w[4] = v1.x; w[5] = v1.y; w[6] = v1.z; w[7] = v1.w;
    } else {
        const int which = (kc < K_BASE + K_SPL) ? 0 : 1;   // 0 = cos coeff, 1 = sin coeff
        const int i = (kc - (which ? (K_BASE + K_SPL) : K_BASE)) >> 3;
        const float* p = cf + (((size_t)which * OUT_DIM + o) * IN_DIM + i) * GRIDSZ;
        float4 v0 = *reinterpret_cast<const float4*>(p);
        float4 v1 = *reinterpret_cast<const float4*>(p + 4);
        const float s = ss[(size_t)o * IN_DIM + i];
        w[0] = v0.x * s; w[1] = v0.y * s; w[2] = v0.z * s; w[3] = v0.w * s;
        w[4] = v1.x * s; w[5] = v1.y * s; w[6] = v1.z * s; w[7] = v1.w * s;
    }
}

__device__ __forceinline__ void mma_tf32(float d[4], const unsigned a[4], const unsigned b[2]) {
    asm volatile(
        "mma.sync.aligned.m16n8k8.row.col.f32.tf32.tf32.f32 "
        "{%0,%1,%2,%3}, {%4,%5,%6,%7}, {%8,%9}, {%0,%1,%2,%3};"
        : "+f"(d[0]), "+f"(d[1]), "+f"(d[2]), "+f"(d[3])
        : "r"(a[0]), "r"(a[1]), "r"(a[2]), "r"(a[3]),
          "r"(b[0]), "r"(b[1]));
}

__global__ void __launch_bounds__(256, 2)
kan_fft_kernel(const float* __restrict__ x,
               const float* __restrict__ sb,   // scale_base   (O, I)
               const float* __restrict__ ss,   // scale_spline (O, I)
               const float* __restrict__ cf,   // coeff        (2, O, I, G)
               float* __restrict__ out)        // (B, O)
{
    __shared__ float SA[BM][SSTRIDE];
    __shared__ float SB[BN][SSTRIDE];

    const int t    = threadIdx.x;
    const int bm   = blockIdx.y * BM;
    const int bn   = blockIdx.x * BN;

    // Tile-fill assignment: thread -> (2 rows) x (8-wide k-chunk)
    const int lrow = t >> 2;          // 0..63
    const int lch  = (t & 3) * 8;     // 0,8,16,24

    // Warp/compute assignment
    const int warp = t >> 5;
    const int lane = t & 31;
    const int wm   = warp & 1;        // 0..1  (64 M rows each)
    const int wn   = warp >> 1;       // 0..3  (32 N cols each)
    const int gID  = lane >> 2;       // 0..7
    const int tg   = lane & 3;        // 0..3

    float acc[4][4][4];
#pragma unroll
    for (int mi = 0; mi < 4; mi++)
#pragma unroll
        for (int ni = 0; ni < 4; ni++)
#pragma unroll
            for (int q = 0; q < 4; q++) acc[mi][ni][q] = 0.0f;

    const float* xr0 = x + (size_t)(bm + lrow)      * IN_DIM;
    const float* xr1 = x + (size_t)(bm + lrow + 64) * IN_DIM;
    const int o0 = bn + lrow;
    const int o1 = bn + lrow + 64;

    for (int k0 = 0; k0 < K_TOT; k0 += BK) {
        const int kc = k0 + lch;
        // ---- A features (tf32 into smem) ----
        {
            float f[8];
            feat8(xr0, kc, f);
#pragma unroll
            for (int j = 0; j < 8; j++) SA[lrow][lch + j] = __uint_as_float(f2tf32(f[j]));
            feat8(xr1, kc, f);
#pragma unroll
            for (int j = 0; j < 8; j++) SA[lrow + 64][lch + j] = __uint_as_float(f2tf32(f[j]));
        }
        // ---- B weights (tf32 into smem) ----
        {
            float w[8];
            wgt8(sb, ss, cf, o0, kc, w);
#pragma unroll
            for (int j = 0; j < 8; j++) SB[lrow][lch + j] = __uint_as_float(f2tf32(w[j]));
            wgt8(sb, ss, cf, o1, kc, w);
#pragma unroll
            for (int j = 0; j < 8; j++) SB[lrow + 64][lch + j] = __uint_as_float(f2tf32(w[j]));
        }
        __syncthreads();

        // ---- compute: 4 k-steps of m16n8k8 ----
#pragma unroll
        for (int ks = 0; ks < 4; ks++) {
            const int kk = ks * 8;
            unsigned a[4][4], b[4][2];
#pragma unroll
            for (int mi = 0; mi < 4; mi++) {
                const int r = wm * 64 + mi * 16 + gID;
                a[mi][0] = __float_as_uint(SA[r    ][kk + tg]);
                a[mi][1] = __float_as_uint(SA[r + 8][kk + tg]);
                a[mi][2] = __float_as_uint(SA[r    ][kk + tg + 4]);
                a[mi][3] = __float_as_uint(SA[r + 8][kk + tg + 4]);
            }
#pragma unroll
            for (int ni = 0; ni < 4; ni++) {
                const int cn = wn * 32 + ni * 8 + gID;
                b[ni][0] = __float_as_uint(SB[cn][kk + tg]);
                b[ni][1] = __float_as_uint(SB[cn][kk + tg + 4]);
            }
#pragma unroll
            for (int mi = 0; mi < 4; mi++)
#pragma unroll
                for (int ni = 0; ni < 4; ni++)
                    mma_tf32(acc[mi][ni], a[mi], b[ni]);
        }
        __syncthreads();
    }

    // ---- epilogue ----
#pragma unroll
    for (int mi = 0; mi < 4; mi++) {
#pragma unroll
        for (int ni = 0; ni < 4; ni++) {
            const int row0 = bm + wm * 64 + mi * 16 + gID;
            const int col  = bn + wn * 32 + ni * 8 + tg * 2;
            float2* p0 = reinterpret_cast<float2*>(out + (size_t)row0 * OUT_DIM + col);
            *p0 = make_float2(acc[mi][ni][0], acc[mi][ni][1]);
            float2* p1 = reinterpret_cast<float2*>(out + (size_t)(row0 + 8) * OUT_DIM + col);
            *p1 = make_float2(acc[mi][ni][2], acc[mi][ni][3]);
        }
    }
}

extern "C" void kernel_launch(void* const* d_in, const int* in_sizes, int n_in,
                              void* d_out, int out_size) {
    const float* x  = (const float*)d_in[0];   // (B, I)
    const float* sb = (const float*)d_in[1];   // (O, I)
    const float* ss = (const float*)d_in[2];   // (O, I)
    const float* cf = (const float*)d_in[3];   // (2, O, I, G)
    float* out = (float*)d_out;

    dim3 grid(OUT_DIM / BN, BATCH / BM);       // (8, 32) = 256 CTAs
    kan_fft_kernel<<<grid, 256>>>(x, sb, ss, cf, out);
}

// round 7
// speedup vs baseline: 1.9611x; 1.9611x over previous
#include <cuda_runtime.h>
#include <cuda_fp16.h>
#include <cstdint>

// ---------------- problem constants ----------------
#define BATCH   4096
#define IN_DIM  1024
#define OUT_DIM 1024
#define GRIDSZ  8
#define K_TOT   17408            // 1024 silu + 1024*16 features (per i: c1..c8, s1..s8)
#define BK      64
#define KTILES  (K_TOT / BK)     // 272
#define BM      128
#define BN      128
#define STAGES  3
#define STAGE_BYTES 32768        // (128+128) rows * 128 bytes
#define SMEM_BYTES  (STAGES * STAGE_BYTES)   // 98304

// ---------------- scratch (static device arrays; no allocation) ----------------
__device__ __align__(16) __half g_A[(size_t)BATCH * K_TOT];    // 142.6 MB
__device__ __align__(16) __half g_B[(size_t)OUT_DIM * K_TOT];  //  35.7 MB

// ---------------- helpers ----------------
static __device__ __forceinline__ uint32_t s2u(const void* p) {
    uint32_t a;
    asm("{ .reg .u64 t; cvta.to.shared.u64 t, %1; cvt.u32.u64 %0, t; }" : "=r"(a) : "l"(p));
    return a;
}
static __device__ __forceinline__ void cp16(uint32_t saddr, const void* gaddr) {
    asm volatile("cp.async.cg.shared.global [%0], [%1], 16;" :: "r"(saddr), "l"(gaddr) : "memory");
}
static __device__ __forceinline__ void cp_commit() {
    asm volatile("cp.async.commit_group;" ::: "memory");
}
static __device__ __forceinline__ void cp_wait1() {
    asm volatile("cp.async.wait_group 1;" ::: "memory");
}
static __device__ __forceinline__ void ldm4(uint32_t* r, uint32_t addr) {
    asm volatile("ldmatrix.sync.aligned.m8n8.x4.shared.b16 {%0,%1,%2,%3}, [%4];"
                 : "=r"(r[0]), "=r"(r[1]), "=r"(r[2]), "=r"(r[3]) : "r"(addr));
}
static __device__ __forceinline__ void mma16816(float* d, const uint32_t* a, uint32_t b0, uint32_t b1) {
    asm volatile("mma.sync.aligned.m16n8k16.row.col.f32.f16.f16.f32 "
                 "{%0,%1,%2,%3}, {%4,%5,%6,%7}, {%8,%9}, {%0,%1,%2,%3};"
                 : "+f"(d[0]), "+f"(d[1]), "+f"(d[2]), "+f"(d[3])
                 : "r"(a[0]), "r"(a[1]), "r"(a[2]), "r"(a[3]), "r"(b0), "r"(b1));
}

// ---------------- kernel 1: build A' features ----------------
// A'[b][k]: k<1024 -> silu(x[b][k]); k = 1024 + i*16 + j -> j<8 ? cos((j+1)x_i) : sin((j-7)x_i)
__global__ void __launch_bounds__(256) build_A(const float* __restrict__ x) {
    const int idx = blockIdx.x * 256 + threadIdx.x;       // 0 .. 4194303
    const int b = idx >> 10;
    const int i = idx & 1023;
    const float xx = x[idx];

    __half* row = g_A + (size_t)b * K_TOT;
    row[i] = __float2half_rn(__fdividef(xx, 1.0f + __expf(-xx)));

    float s1, c1;
    __sincosf(xx, &s1, &c1);
    float ca[8], sa[8];
    ca[0] = c1; sa[0] = s1;
    float cg = c1, sg = s1;
#pragma unroll
    for (int j = 1; j < 8; j++) {
        float cn = cg * c1 - sg * s1;
        float sn = sg * c1 + cg * s1;
        cg = cn; sg = sn;
        ca[j] = cg; sa[j] = sg;
    }
    __half2 h[8];
#pragma unroll
    for (int j = 0; j < 4; j++) h[j]     = __floats2half2_rn(ca[2*j], ca[2*j+1]);
#pragma unroll
    for (int j = 0; j < 4; j++) h[4 + j] = __floats2half2_rn(sa[2*j], sa[2*j+1]);
    uint4* dst = reinterpret_cast<uint4*>(row + 1024 + i * 16);
    dst[0] = *reinterpret_cast<const uint4*>(h);
    dst[1] = *reinterpret_cast<const uint4*>(h + 4);
}

// ---------------- kernel 2: build B' weights ----------------
__global__ void __launch_bounds__(256) build_B(const float* __restrict__ sb,
                                               const float* __restrict__ ss,
                                               const float* __restrict__ cf) {
    const int idx = blockIdx.x * 256 + threadIdx.x;       // 0 .. 1048575
    const int o = idx >> 10;
    const int i = idx & 1023;

    __half* row = g_B + (size_t)o * K_TOT;
    row[i] = __float2half_rn(sb[idx]);

    const float w = ss[idx];
    const float4* c0 = reinterpret_cast<const float4*>(cf + ((size_t)o * IN_DIM + i) * GRIDSZ);
    const float4* c1 = reinterpret_cast<const float4*>(cf + (((size_t)OUT_DIM + o) * IN_DIM + i) * GRIDSZ);
    float4 a0 = c0[0], a1 = c0[1];
    float4 b0 = c1[0], b1 = c1[1];
    __half2 h[8];
    h[0] = __floats2half2_rn(a0.x * w, a0.y * w);
    h[1] = __floats2half2_rn(a0.z * w, a0.w * w);
    h[2] = __floats2half2_rn(a1.x * w, a1.y * w);
    h[3] = __floats2half2_rn(a1.z * w, a1.w * w);
    h[4] = __floats2half2_rn(b0.x * w, b0.y * w);
    h[5] = __floats2half2_rn(b0.z * w, b0.w * w);
    h[6] = __floats2half2_rn(b1.x * w, b1.y * w);
    h[7] = __floats2half2_rn(b1.z * w, b1.w * w);
    uint4* dst = reinterpret_cast<uint4*>(row + 1024 + i * 16);
    dst[0] = *reinterpret_cast<const uint4*>(h);
    dst[1] = *reinterpret_cast<const uint4*>(h + 4);
}

// ---------------- kernel 3: fp16 GEMM  out = A' * B'^T ----------------
__global__ void __launch_bounds__(256, 2) gemm_fp16(float* __restrict__ out) {
    extern __shared__ char smem[];
    const uint32_t sbase = s2u(smem);

    const int tid  = threadIdx.x;
    const int warp = tid >> 5;
    const int lane = tid & 31;
    const int bm = blockIdx.y * BM;
    const int bn = blockIdx.x * BN;

    // ---- cp.async mapping: thread -> (row, 64B half-row) for A and B ----
    const int lr = tid >> 1;          // 0..127
    const int lh = tid & 1;           // 0..1
    const __half* gA = g_A + (size_t)(bm + lr) * K_TOT + lh * 32;
    const __half* gB = g_B + (size_t)(bn + lr) * K_TOT + lh * 32;
    uint32_t saOff[4], sbOff[4];
#pragma unroll
    for (int j = 0; j < 4; j++) {
        const int kc = lh * 4 + j;                         // 16B chunk index 0..7
        saOff[j] = (uint32_t)(lr * 128 + ((kc ^ (lr & 7)) * 16));
        sbOff[j] = saOff[j] + 16384u;
    }

    // ---- compute mapping ----
    const int wm  = warp & 1;         // 0..1  (64 rows each)
    const int wn  = warp >> 1;        // 0..3  (32 cols each)
    const int gID = lane >> 2;
    const int tg  = lane & 3;
    const int l15 = lane & 15;
    const int cs  = lane >> 4;        // 0/1: selects k-halves 0-7 vs 8-15

    // Separate base / swizzle-key registers (bits MUST NOT be packed: r*128
    // occupies bits 7..13, overlapping any key placed at bits 8..10).
    uint32_t aBase[4], aKey[4], bBase[2], bKey[2];
#pragma unroll
    for (int mi = 0; mi < 4; mi++) {
        const int r = wm * 64 + mi * 16 + l15;
        aBase[mi] = (uint32_t)(r * 128);
        aKey[mi]  = (uint32_t)(r & 7);
    }
#pragma unroll
    for (int nb = 0; nb < 2; nb++) {
        const int r = wn * 32 + nb * 16 + l15;
        bBase[nb] = (uint32_t)(r * 128) + 16384u;
        bKey[nb]  = (uint32_t)(r & 7);
    }

    float acc[4][4][4];
#pragma unroll
    for (int mi = 0; mi < 4; mi++)
#pragma unroll
        for (int ni = 0; ni < 4; ni++)
#pragma unroll
            for (int q = 0; q < 4; q++) acc[mi][ni][q] = 0.0f;

    // ---- prologue: stages 0,1 ----
#pragma unroll
    for (int s = 0; s < 2; s++) {
        const uint32_t st = sbase + s * STAGE_BYTES;
        const __half* pa = gA + s * BK;
        const __half* pb = gB + s * BK;
#pragma unroll
        for (int j = 0; j < 4; j++) {
            cp16(st + saOff[j], pa + j * 8);
            cp16(st + sbOff[j], pb + j * 8);
        }
        cp_commit();
    }

    // ---- mainloop ----
#pragma unroll 1
    for (int kt = 0; kt < KTILES; kt++) {
        cp_wait1();
        __syncthreads();

        const int ktn = kt + 2;
        if (ktn < KTILES) {
            const uint32_t st = sbase + (ktn % STAGES) * STAGE_BYTES;
            const __half* pa = gA + ktn * BK;
            const __half* pb = gB + ktn * BK;
#pragma unroll
            for (int j = 0; j < 4; j++) {
                cp16(st + saOff[j], pa + j * 8);
                cp16(st + sbOff[j], pb + j * 8);
            }
        }
        cp_commit();

        const uint32_t st = sbase + (kt % STAGES) * STAGE_BYTES;
#pragma unroll
        for (int ks = 0; ks < 4; ks++) {
            uint32_t a[4][4], b[2][4];
#pragma unroll
            for (int mi = 0; mi < 4; mi++)
                ldm4(a[mi], st + aBase[mi] + (((uint32_t)(2 * ks + cs) ^ aKey[mi]) * 16));
#pragma unroll
            for (int nb = 0; nb < 2; nb++)
                ldm4(b[nb], st + bBase[nb] + (((uint32_t)(2 * ks + cs) ^ bKey[nb]) * 16));
#pragma unroll
            for (int mi = 0; mi < 4; mi++) {
#pragma unroll
                for (int nb = 0; nb < 2; nb++) {
                    // b[nb]: {n0-7,k0-7}, {n8-15,k0-7}, {n0-7,k8-15}, {n8-15,k8-15}
                    mma16816(acc[mi][2 * nb],     a[mi], b[nb][0], b[nb][2]);
                    mma16816(acc[mi][2 * nb + 1], a[mi], b[nb][1], b[nb][3]);
                }
            }
        }
    }

    // ---- epilogue ----
#pragma unroll
    for (int mi = 0; mi < 4; mi++) {
        const int row0 = bm + wm * 64 + mi * 16 + gID;
#pragma unroll
        for (int ni = 0; ni < 4; ni++) {
            const int col = bn + wn * 32 + ni * 8 + tg * 2;
            *reinterpret_cast<float2*>(out + (size_t)row0 * OUT_DIM + col) =
                make_float2(acc[mi][ni][0], acc[mi][ni][1]);
            *reinterpret_cast<float2*>(out + (size_t)(row0 + 8) * OUT_DIM + col) =
                make_float2(acc[mi][ni][2], acc[mi][ni][3]);
        }
    }
}

// ---------------- host launch ----------------
extern "C" void kernel_launch(void* const* d_in, const int* in_sizes, int n_in,
                              void* d_out, int out_size) {
    const float* x  = (const float*)d_in[0];
    const float* sb = (const float*)d_in[1];
    const float* ss = (const float*)d_in[2];
    const float* cf = (const float*)d_in[3];
    float* out = (float*)d_out;

    cudaFuncSetAttribute(gemm_fp16, cudaFuncAttributeMaxDynamicSharedMemorySize, SMEM_BYTES);

    build_A<<<(BATCH * IN_DIM) / 256, 256>>>(x);
    build_B<<<(OUT_DIM * IN_DIM) / 256, 256>>>(sb, ss, cf);
    dim3 grid(OUT_DIM / BN, BATCH / BM);   // (8, 32)
    gemm_fp16<<<grid, 256, SMEM_BYTES>>>(out);
}